// round 1
// baseline (speedup 1.0000x reference)
#include <cuda_runtime.h>
#include <cuda_bf16.h>

// Problem constants
#define BATCH 1024
#define DIN   512
#define HID   512
#define DOUT  512
#define NB    8      // batch rows per scan CTA

// scratch for hidden activations
__device__ float g_h[BATCH * HID];

// ---------------------------------------------------------------------------
// Tiled fp32 GEMM: C[M,N] = act?(A[M,K] @ W[K,N] + bias[N])
// 64x64 tile, 256 threads, 4x4 per thread, K-tile 16.
// ---------------------------------------------------------------------------
__global__ __launch_bounds__(256) void gemm_kernel(
    const float* __restrict__ A, const float* __restrict__ W,
    const float* __restrict__ bias, float* __restrict__ C,
    int M, int N, int K, int act)
{
    __shared__ float As[16][64];   // k-major: As[kk][row]
    __shared__ float Ws[16][64];   // Ws[kk][col]

    const int t  = threadIdx.x;
    const int bx = blockIdx.x;     // N tile
    const int by = blockIdx.y;     // M tile
    const int tx = t & 15;         // 0..15
    const int ty = t >> 4;         // 0..15

    // A-tile loading assignment: each thread loads one float4 (4 consecutive k)
    const int arow = t >> 2;       // 0..63
    const int aq   = t & 3;        // 0..3  -> k offset aq*4
    // W-tile loading assignment: each thread loads one float4 (4 consecutive n)
    const int wk   = t >> 4;       // 0..15
    const int wq   = t & 15;       // 0..15 -> n offset wq*4

    const float* Aptr = A + (size_t)(by * 64 + arow) * K + aq * 4;
    const float* Wptr = W + (size_t)wk * N + bx * 64 + wq * 4;

    float acc[4][4];
    #pragma unroll
    for (int i = 0; i < 4; i++)
        #pragma unroll
        for (int j = 0; j < 4; j++) acc[i][j] = 0.0f;

    for (int k0 = 0; k0 < K; k0 += 16) {
        float4 av = *(const float4*)Aptr;  Aptr += 16;
        float4 wv = *(const float4*)Wptr;  Wptr += (size_t)16 * N;

        __syncthreads();   // previous tile's compute done
        As[aq * 4 + 0][arow] = av.x;
        As[aq * 4 + 1][arow] = av.y;
        As[aq * 4 + 2][arow] = av.z;
        As[aq * 4 + 3][arow] = av.w;
        *(float4*)&Ws[wk][wq * 4] = wv;
        __syncthreads();

        #pragma unroll
        for (int kk = 0; kk < 16; kk++) {
            float4 a4 = *(const float4*)&As[kk][ty * 4];
            float4 w4 = *(const float4*)&Ws[kk][tx * 4];
            float a[4] = {a4.x, a4.y, a4.z, a4.w};
            float w[4] = {w4.x, w4.y, w4.z, w4.w};
            #pragma unroll
            for (int i = 0; i < 4; i++)
                #pragma unroll
                for (int j = 0; j < 4; j++)
                    acc[i][j] = fmaf(a[i], w[j], acc[i][j]);
        }
    }

    const int row = by * 64 + ty * 4;
    const int col = bx * 64 + tx * 4;
    float bl[4];
    #pragma unroll
    for (int j = 0; j < 4; j++) bl[j] = bias[col + j];

    #pragma unroll
    for (int i = 0; i < 4; i++) {
        float4 o;
        float* op = &o.x;
        #pragma unroll
        for (int j = 0; j < 4; j++) {
            float v = acc[i][j] + bl[j];
            if (act) { float r = fmaxf(v, 0.0f); v = r * r; }
            op[j] = v;
        }
        *(float4*)&C[(size_t)(row + i) * N + col] = o;
    }
}

// ---------------------------------------------------------------------------
// Sequential scan: h[:,j] += relu^2(h[:,i]*Whh[i,j] + Bhh[i,j]) for j > i,
// i = 0..H-2, with h[:,i] being the fully-updated value (strict sequence).
// CTA = NB batch rows, thread j owns column j's NB accumulators in registers.
// Double-buffered broadcast slot => one __syncthreads per step.
// ---------------------------------------------------------------------------
__global__ __launch_bounds__(512) void scan_kernel(
    const float* __restrict__ Whh, const float* __restrict__ Bhh)
{
    const int j    = threadIdx.x;          // column 0..511
    const int row0 = blockIdx.x * NB;

    __shared__ float s[2][NB];

    float h[NB];
    #pragma unroll
    for (int b = 0; b < NB; b++)
        h[b] = g_h[(size_t)(row0 + b) * HID + j];

    if (j == 0) {
        #pragma unroll
        for (int b = 0; b < NB; b++) s[0][b] = h[b];
    }

    // prefetch row 0 of W/b
    float w  = Whh[j];
    float bb = Bhh[j];

    for (int i = 0; i < HID - 1; i++) {
        __syncthreads();   // publish of s[i&1] visible; s[(i+1)&1] readers done

        // prefetch next row while this step computes
        float wn = 0.0f, bn = 0.0f;
        if (i + 1 < HID - 1) {
            wn = Whh[(size_t)(i + 1) * HID + j];
            bn = Bhh[(size_t)(i + 1) * HID + j];
        }

        if (j > i) {
            const float* sp = s[i & 1];
            #pragma unroll
            for (int b = 0; b < NB; b++) {
                float v = fmaf(sp[b], w, bb);
                float r = fmaxf(v, 0.0f);
                h[b] = fmaf(r, r, h[b]);
            }
        }
        if (j == i + 1) {
            float* sq = s[(i + 1) & 1];
            #pragma unroll
            for (int b = 0; b < NB; b++) sq[b] = h[b];
        }
        w = wn; bb = bn;
    }

    #pragma unroll
    for (int b = 0; b < NB; b++)
        g_h[(size_t)(row0 + b) * HID + j] = h[b];
}

// ---------------------------------------------------------------------------
// Launch
// ---------------------------------------------------------------------------
extern "C" void kernel_launch(void* const* d_in, const int* in_sizes, int n_in,
                              void* d_out, int out_size)
{
    const float* x     = (const float*)d_in[0];  // [1024, 512]
    const float* W_in  = (const float*)d_in[1];  // [512, 512]
    const float* b_in  = (const float*)d_in[2];  // [512]
    const float* W_hh  = (const float*)d_in[3];  // [511, 512]
    const float* b_hh  = (const float*)d_in[4];  // [511, 512]
    const float* W_out = (const float*)d_in[5];  // [512, 512]
    const float* b_out = (const float*)d_in[6];  // [512]
    float* out = (float*)d_out;                  // [1024, 512]

    float* hptr = nullptr;
    cudaGetSymbolAddress((void**)&hptr, g_h);

    dim3 gblk(256);
    dim3 ggrid(HID / 64, BATCH / 64);

    // h0 = relu^2(x @ W_in + b_in)
    gemm_kernel<<<ggrid, gblk>>>(x, W_in, b_in, hptr, BATCH, HID, DIN, 1);

    // sequential column scan (in-place on g_h)
    scan_kernel<<<BATCH / NB, 512>>>(W_hh, b_hh);

    // out = h @ W_out + b_out
    dim3 ogrid(DOUT / 64, BATCH / 64);
    gemm_kernel<<<ogrid, gblk>>>(hptr, W_out, b_out, out, BATCH, DOUT, HID, 0);
}

// round 2
// speedup vs baseline: 1.0154x; 1.0154x over previous
#include <cuda_runtime.h>
#include <cuda_bf16.h>

#define BATCH 1024
#define DIN   512
#define HID   512
#define DOUT  512
#define NB    8      // batch rows per scan CTA
#define CH    32     // scan chunk width (1 warp)
#define NCH   (HID / CH)

typedef unsigned long long u64;

__device__ float g_h[BATCH * HID];

__device__ __forceinline__ u64 pack2(float v) {
    u64 r;
    asm("mov.b64 %0, {%1, %1};" : "=l"(r) : "f"(v));
    return r;
}
__device__ __forceinline__ void ffma2(u64& d, u64 a, u64 b) {
    asm("fma.rn.f32x2 %0, %1, %2, %0;" : "+l"(d) : "l"(a), "l"(b));
}

// ---------------------------------------------------------------------------
// fp32 GEMM with packed f32x2 FMA: C = act?(A[M,K] @ W[K,N] + bias)
// 64x64 tile, 256 threads, 4 rows x 4 cols (2 packed col-pairs) per thread.
// A tile staged DUPLICATED ({v,v}) in smem so the inner loop has no packs.
// ---------------------------------------------------------------------------
__global__ __launch_bounds__(256) void gemm_kernel(
    const float* __restrict__ A, const float* __restrict__ W,
    const float* __restrict__ bias, float* __restrict__ C,
    int M, int N, int K, int act)
{
    __shared__ u64 As2[16][64];                    // duplicated A: [kk][row]
    __shared__ __align__(16) float Ws[16][64];     // [kk][col]

    const int t  = threadIdx.x;
    const int bx = blockIdx.x;
    const int by = blockIdx.y;
    const int tx = t & 15;         // col group
    const int ty = t >> 4;         // row group

    const int arow = t >> 2;       // A staging: row 0..63
    const int aq   = t & 3;        // k quad
    const int wk   = t >> 4;       // W staging: k 0..15
    const int wq   = t & 15;       // n quad

    const float* Aptr = A + (size_t)(by * 64 + arow) * K + aq * 4;
    const float* Wptr = W + (size_t)wk * N + bx * 64 + wq * 4;

    u64 acc[4][2];
    #pragma unroll
    for (int i = 0; i < 4; i++) { acc[i][0] = 0ull; acc[i][1] = 0ull; }

    for (int k0 = 0; k0 < K; k0 += 16) {
        float4 av = *(const float4*)Aptr;  Aptr += 16;
        float4 wv = *(const float4*)Wptr;  Wptr += (size_t)16 * N;

        __syncthreads();
        As2[aq * 4 + 0][arow] = pack2(av.x);
        As2[aq * 4 + 1][arow] = pack2(av.y);
        As2[aq * 4 + 2][arow] = pack2(av.z);
        As2[aq * 4 + 3][arow] = pack2(av.w);
        *(float4*)&Ws[wk][wq * 4] = wv;
        __syncthreads();

        #pragma unroll
        for (int kk = 0; kk < 16; kk++) {
            ulonglong2 w2 = *(const ulonglong2*)&Ws[kk][tx * 4];
            #pragma unroll
            for (int i = 0; i < 4; i++) {
                u64 ad = As2[kk][ty * 4 + i];
                ffma2(acc[i][0], ad, w2.x);
                ffma2(acc[i][1], ad, w2.y);
            }
        }
    }

    const int row = by * 64 + ty * 4;
    const int col = bx * 64 + tx * 4;
    float bl[4];
    #pragma unroll
    for (int j = 0; j < 4; j++) bl[j] = bias[col + j];

    #pragma unroll
    for (int i = 0; i < 4; i++) {
        float2 p0 = reinterpret_cast<float2&>(acc[i][0]);
        float2 p1 = reinterpret_cast<float2&>(acc[i][1]);
        float v[4] = {p0.x, p0.y, p1.x, p1.y};
        float4 o;
        float* op = &o.x;
        #pragma unroll
        for (int j = 0; j < 4; j++) {
            float s = v[j] + bl[j];
            if (act) { float r = fmaxf(s, 0.0f); s = r * r; }
            op[j] = s;
        }
        *(float4*)&C[(size_t)(row + i) * N + col] = o;
    }
}

// ---------------------------------------------------------------------------
// Chunked sequential scan.
// h[:,j] += relu^2(h[:,i]*Whh[i,j] + Bhh[i,j]) for j > i, i = 0..HID-2,
// with h[:,i] fully updated before use (strict order).
//
// 16 chunks of 32 columns. Warp c does the 32 sequential steps of chunk c
// intra-warp via shuffles (W/b rows preloaded into registers), publishes the
// 32 finalized columns to smem, and all higher warps apply the 32 updates in
// bulk. 16 block barriers total instead of 511.
// ---------------------------------------------------------------------------
__global__ __launch_bounds__(512) void scan_kernel(
    const float* __restrict__ Whh, const float* __restrict__ Bhh)
{
    const int j    = threadIdx.x;          // column 0..511
    const int w    = j >> 5;               // warp / chunk id
    const int l    = j & 31;               // lane
    const int row0 = blockIdx.x * NB;

    __shared__ float bc[2][CH][NB];        // published chunk values

    float h[NB];
    #pragma unroll
    for (int b = 0; b < NB; b++)
        h[b] = g_h[(size_t)(row0 + b) * HID + j];

    // Preload this warp's own chunk W/B rows: Whh[32w + il][j] for il=0..31.
    const int cbase = w << 5;
    float wr[CH], br[CH];
    #pragma unroll
    for (int il = 0; il < CH; il++) {
        int i = cbase + il;
        bool valid = (i < HID - 1);
        wr[il] = valid ? Whh[(size_t)i * HID + j] : 0.0f;
        br[il] = valid ? Bhh[(size_t)i * HID + j] : 0.0f;
    }

    for (int c = 0; c < NCH; c++) {
        if (w == c) {
            // intra-warp sequential scan of this chunk
            #pragma unroll
            for (int il = 0; il < CH; il++) {
                int i = cbase + il;
                float s[NB];
                #pragma unroll
                for (int b = 0; b < NB; b++)
                    s[b] = __shfl_sync(0xffffffffu, h[b], il);
                if (l > il && i < HID - 1) {
                    #pragma unroll
                    for (int b = 0; b < NB; b++) {
                        float v = fmaf(s[b], wr[il], br[il]);
                        float r = fmaxf(v, 0.0f);
                        h[b] = fmaf(r, r, h[b]);
                    }
                }
            }
            // publish finalized columns + write final result
            #pragma unroll
            for (int b = 0; b < NB; b++) bc[c & 1][l][b] = h[b];
            #pragma unroll
            for (int b = 0; b < NB; b++)
                g_h[(size_t)(row0 + b) * HID + j] = h[b];
        }
        __syncthreads();
        if (w > c) {
            // bulk-apply the 32 updates of chunk c (all valid: i <= 479 < 511)
            const int base = c << 5;
            #pragma unroll 4
            for (int il = 0; il < CH; il++) {
                int i = base + il;
                float wv = Whh[(size_t)i * HID + j];
                float bv = Bhh[(size_t)i * HID + j];
                #pragma unroll
                for (int b = 0; b < NB; b++) {
                    float v = fmaf(bc[c & 1][il][b], wv, bv);
                    float r = fmaxf(v, 0.0f);
                    h[b] = fmaf(r, r, h[b]);
                }
            }
        }
        // double buffer + single barrier: next publish targets the other slot
    }
}

// ---------------------------------------------------------------------------
extern "C" void kernel_launch(void* const* d_in, const int* in_sizes, int n_in,
                              void* d_out, int out_size)
{
    const float* x     = (const float*)d_in[0];
    const float* W_in  = (const float*)d_in[1];
    const float* b_in  = (const float*)d_in[2];
    const float* W_hh  = (const float*)d_in[3];
    const float* b_hh  = (const float*)d_in[4];
    const float* W_out = (const float*)d_in[5];
    const float* b_out = (const float*)d_in[6];
    float* out = (float*)d_out;

    float* hptr = nullptr;
    cudaGetSymbolAddress((void**)&hptr, g_h);

    dim3 gblk(256);
    dim3 ggrid(HID / 64, BATCH / 64);
    gemm_kernel<<<ggrid, gblk>>>(x, W_in, b_in, hptr, BATCH, HID, DIN, 1);

    scan_kernel<<<BATCH / NB, 512>>>(W_hh, b_hh);

    dim3 ogrid(DOUT / 64, BATCH / 64);
    gemm_kernel<<<ogrid, gblk>>>(hptr, W_out, b_out, out, BATCH, DOUT, HID, 0);
}

// round 3
// speedup vs baseline: 1.3888x; 1.3678x over previous
#include <cuda_runtime.h>
#include <cuda_bf16.h>

#define BATCH 1024
#define DIN   512
#define HID   512
#define DOUT  512
#define NB    8      // batch rows per scan CTA
#define CH    32     // scan chunk width (1 warp)
#define NCH   (HID / CH)

__device__ float g_h[BATCH * HID];

// ---------------------------------------------------------------------------
// fp32 GEMM: C = act?(A[M,K] @ W[K,N] + bias)
// 64x64 tile, 256 threads, 4x4 per thread, K-tile 16.
// Double-buffered smem, ONE __syncthreads per k-tile, LDG prefetch overlapped.
// ---------------------------------------------------------------------------
__global__ __launch_bounds__(256) void gemm_kernel(
    const float* __restrict__ A, const float* __restrict__ W,
    const float* __restrict__ bias, float* __restrict__ C,
    int M, int N, int K, int act)
{
    __shared__ float As[2][16][64];   // k-major: [buf][kk][row]
    __shared__ float Ws[2][16][64];   // [buf][kk][col]

    const int t  = threadIdx.x;
    const int bx = blockIdx.x;
    const int by = blockIdx.y;
    const int tx = t & 15;
    const int ty = t >> 4;

    const int arow = t >> 2;       // A staging row 0..63
    const int aq   = t & 3;        // k quad
    const int wk   = t >> 4;       // W staging k 0..15
    const int wq   = t & 15;       // n quad

    const float* Aptr = A + (size_t)(by * 64 + arow) * K + aq * 4;
    const float* Wptr = W + (size_t)wk * N + bx * 64 + wq * 4;

    // prologue: load + stage tile 0
    float4 av = *(const float4*)Aptr;  Aptr += 16;
    float4 wv = *(const float4*)Wptr;  Wptr += (size_t)16 * N;
    As[0][aq * 4 + 0][arow] = av.x;
    As[0][aq * 4 + 1][arow] = av.y;
    As[0][aq * 4 + 2][arow] = av.z;
    As[0][aq * 4 + 3][arow] = av.w;
    *(float4*)&Ws[0][wk][wq * 4] = wv;

    float acc[4][4];
    #pragma unroll
    for (int i = 0; i < 4; i++)
        #pragma unroll
        for (int jj = 0; jj < 4; jj++) acc[i][jj] = 0.0f;

    const int NT = K / 16;
    for (int kt = 0; kt < NT; kt++) {
        __syncthreads();   // staged tile kt visible; prev compute done

        float4 av2, wv2;
        if (kt + 1 < NT) {
            av2 = *(const float4*)Aptr;  Aptr += 16;
            wv2 = *(const float4*)Wptr;  Wptr += (size_t)16 * N;
        }

        const int cb = kt & 1;
        #pragma unroll
        for (int kk = 0; kk < 16; kk++) {
            float4 a4 = *(const float4*)&As[cb][kk][ty * 4];
            float4 w4 = *(const float4*)&Ws[cb][kk][tx * 4];
            float a[4] = {a4.x, a4.y, a4.z, a4.w};
            float w[4] = {w4.x, w4.y, w4.z, w4.w};
            #pragma unroll
            for (int i = 0; i < 4; i++)
                #pragma unroll
                for (int jj = 0; jj < 4; jj++)
                    acc[i][jj] = fmaf(a[i], w[jj], acc[i][jj]);
        }

        if (kt + 1 < NT) {
            const int nb = (kt + 1) & 1;
            As[nb][aq * 4 + 0][arow] = av2.x;
            As[nb][aq * 4 + 1][arow] = av2.y;
            As[nb][aq * 4 + 2][arow] = av2.z;
            As[nb][aq * 4 + 3][arow] = av2.w;
            *(float4*)&Ws[nb][wk][wq * 4] = wv2;
        }
    }

    const int row = by * 64 + ty * 4;
    const int col = bx * 64 + tx * 4;
    float bl[4];
    #pragma unroll
    for (int jj = 0; jj < 4; jj++) bl[jj] = bias[col + jj];

    #pragma unroll
    for (int i = 0; i < 4; i++) {
        float4 o;
        float* op = &o.x;
        #pragma unroll
        for (int jj = 0; jj < 4; jj++) {
            float v = acc[i][jj] + bl[jj];
            if (act) { float r = fmaxf(v, 0.0f); v = r * r; }
            op[jj] = v;
        }
        *(float4*)&C[(size_t)(row + i) * N + col] = o;
    }
}

// ---------------------------------------------------------------------------
// Flag-pipelined sequential scan.
// h[:,j] += relu^2(h[:,i]*Whh[i,j] + Bhh[i,j]) for j > i, strict order in i.
// 16 chunks of 32 columns, one warp per chunk. Warp w:
//   for c in 0..w-1: prefetch W/b rows of chunk c (LDG overlaps flag wait),
//                    spin on flag[c], bulk-apply chunk c's published values.
//   then intra-warp shuffle-scan its own 32 columns, publish bc[w]+flag[w],
//   store final columns, exit.
// No __syncthreads in the pipeline -> chunks overlap across warps.
// ---------------------------------------------------------------------------
__global__ __launch_bounds__(512) void scan_kernel(
    const float* __restrict__ Whh, const float* __restrict__ Bhh)
{
    const int j    = threadIdx.x;          // column 0..511
    const int w    = j >> 5;               // warp / chunk id
    const int l    = j & 31;               // lane
    const int row0 = blockIdx.x * NB;

    __shared__ float bc[NCH][CH][NB];      // published finalized chunk values
    __shared__ int   flag[NCH];

    if (j < NCH) flag[j] = 0;
    __syncthreads();
    volatile int* vflag = flag;

    float h[NB];
    #pragma unroll
    for (int b = 0; b < NB; b++)
        h[b] = g_h[(size_t)(row0 + b) * HID + j];

    // ---- apply earlier chunks as they are published ----
    for (int c = 0; c < w; c++) {
        const int base = c << 5;
        float wv[CH], bv[CH];
        #pragma unroll
        for (int il = 0; il < CH; il++) {   // prefetch BEFORE flag wait
            wv[il] = Whh[(size_t)(base + il) * HID + j];
            bv[il] = Bhh[(size_t)(base + il) * HID + j];
        }
        while (vflag[c] == 0) { }
        __threadfence_block();
        #pragma unroll
        for (int il = 0; il < CH; il++) {
            float4 p0 = *(const float4*)&bc[c][il][0];   // warp-broadcast
            float4 p1 = *(const float4*)&bc[c][il][4];
            float s[NB] = {p0.x, p0.y, p0.z, p0.w, p1.x, p1.y, p1.z, p1.w};
            #pragma unroll
            for (int b = 0; b < NB; b++) {
                float v = fmaf(s[b], wv[il], bv[il]);
                float r = fmaxf(v, 0.0f);
                h[b] = fmaf(r, r, h[b]);
            }
        }
    }

    // ---- intra-warp sequential scan of own chunk (2 halves of 16 -> regs) ----
    const int cbase = w << 5;
    #pragma unroll
    for (int half = 0; half < 2; half++) {
        float wr[16], br[16];
        #pragma unroll
        for (int q = 0; q < 16; q++) {
            int i = cbase + half * 16 + q;
            bool valid = (i < HID - 1);
            wr[q] = valid ? Whh[(size_t)i * HID + j] : 0.0f;
            br[q] = valid ? Bhh[(size_t)i * HID + j] : 0.0f;
        }
        #pragma unroll
        for (int q = 0; q < 16; q++) {
            const int il = half * 16 + q;
            float s[NB];
            #pragma unroll
            for (int b = 0; b < NB; b++)
                s[b] = __shfl_sync(0xffffffffu, h[b], il);
            if (l > il) {
                #pragma unroll
                for (int b = 0; b < NB; b++) {
                    float v = fmaf(s[b], wr[q], br[q]);
                    float r = fmaxf(v, 0.0f);
                    h[b] = fmaf(r, r, h[b]);
                }
            }
        }
    }

    // ---- publish + final store ----
    if (w < NCH - 1) {
        *(float4*)&bc[w][l][0] = make_float4(h[0], h[1], h[2], h[3]);
        *(float4*)&bc[w][l][4] = make_float4(h[4], h[5], h[6], h[7]);
        __threadfence_block();
        if (l == 0) vflag[w] = 1;
    }
    #pragma unroll
    for (int b = 0; b < NB; b++)
        g_h[(size_t)(row0 + b) * HID + j] = h[b];
}

// ---------------------------------------------------------------------------
extern "C" void kernel_launch(void* const* d_in, const int* in_sizes, int n_in,
                              void* d_out, int out_size)
{
    const float* x     = (const float*)d_in[0];
    const float* W_in  = (const float*)d_in[1];
    const float* b_in  = (const float*)d_in[2];
    const float* W_hh  = (const float*)d_in[3];
    const float* b_hh  = (const float*)d_in[4];
    const float* W_out = (const float*)d_in[5];
    const float* b_out = (const float*)d_in[6];
    float* out = (float*)d_out;

    float* hptr = nullptr;
    cudaGetSymbolAddress((void**)&hptr, g_h);

    dim3 gblk(256);
    dim3 ggrid(HID / 64, BATCH / 64);
    gemm_kernel<<<ggrid, gblk>>>(x, W_in, b_in, hptr, BATCH, HID, DIN, 1);

    scan_kernel<<<BATCH / NB, 512>>>(W_hh, b_hh);

    dim3 ogrid(DOUT / 64, BATCH / 64);
    gemm_kernel<<<ogrid, gblk>>>(hptr, W_out, b_out, out, BATCH, DOUT, HID, 0);
}

// round 4
// speedup vs baseline: 1.6581x; 1.1939x over previous
#include <cuda_runtime.h>
#include <cuda_bf16.h>

#define BATCH 1024
#define DIN   512
#define HID   512
#define DOUT  512
#define NB    8      // batch rows per scan CTA
#define CH    32     // scan chunk width (1 warp)
#define NCH   (HID / CH)

typedef unsigned long long u64;

__device__ float g_h[BATCH * HID];

// ---- packed f32x2 helpers -------------------------------------------------
__device__ __forceinline__ u64 pack2(float v) {           // {v, v}
    u64 r; asm("mov.b64 %0, {%1, %1};" : "=l"(r) : "f"(v)); return r;
}
__device__ __forceinline__ u64 packxy(float x, float y) { // {x, y}
    u64 r; asm("mov.b64 %0, {%1, %2};" : "=l"(r) : "f"(x), "f"(y)); return r;
}
__device__ __forceinline__ float2 unpk(u64 v) {
    float2 f; asm("mov.b64 {%0, %1}, %2;" : "=f"(f.x), "=f"(f.y) : "l"(v)); return f;
}
__device__ __forceinline__ void ffma2(u64& d, u64 a, u64 b) {
    asm("fma.rn.f32x2 %0, %1, %2, %0;" : "+l"(d) : "l"(a), "l"(b));
}
__device__ __forceinline__ u64 fma2v(u64 a, u64 b, u64 c) {
    u64 d; asm("fma.rn.f32x2 %0, %1, %2, %3;" : "=l"(d) : "l"(a), "l"(b), "l"(c)); return d;
}
__device__ __forceinline__ u64 max2z(u64 v) {             // per-component max(v,0)
    u64 m;
    asm("{\n\t.reg .f32 a, b;\n\t"
        "mov.b64 {a, b}, %1;\n\t"
        "max.f32 a, a, 0f00000000;\n\t"
        "max.f32 b, b, 0f00000000;\n\t"
        "mov.b64 %0, {a, b};\n\t}"
        : "=l"(m) : "l"(v));
    return m;
}

// ---------------------------------------------------------------------------
// fp32 GEMM: C = act?(A[M,K] @ W[K,N] + bias)
// 64x64 tile, 256 threads, 4 rows x 4 cols per thread (2 packed col-pairs).
// Double-buffered smem, one barrier per k-tile; FFMA2 with in-register A dup.
// ---------------------------------------------------------------------------
__global__ __launch_bounds__(256) void gemm_kernel(
    const float* __restrict__ A, const float* __restrict__ W,
    const float* __restrict__ bias, float* __restrict__ C,
    int M, int N, int K, int act)
{
    __shared__ __align__(16) float As[2][16][64];   // k-major: [buf][kk][row]
    __shared__ __align__(16) float Ws[2][16][64];   // [buf][kk][col]

    const int t  = threadIdx.x;
    const int bx = blockIdx.x;
    const int by = blockIdx.y;
    const int tx = t & 15;
    const int ty = t >> 4;

    const int arow = t >> 2;
    const int aq   = t & 3;
    const int wk   = t >> 4;
    const int wq   = t & 15;

    const float* Aptr = A + (size_t)(by * 64 + arow) * K + aq * 4;
    const float* Wptr = W + (size_t)wk * N + bx * 64 + wq * 4;

    float4 av = *(const float4*)Aptr;  Aptr += 16;
    float4 wv = *(const float4*)Wptr;  Wptr += (size_t)16 * N;
    As[0][aq * 4 + 0][arow] = av.x;
    As[0][aq * 4 + 1][arow] = av.y;
    As[0][aq * 4 + 2][arow] = av.z;
    As[0][aq * 4 + 3][arow] = av.w;
    *(float4*)&Ws[0][wk][wq * 4] = wv;

    u64 acc[4][2];
    #pragma unroll
    for (int i = 0; i < 4; i++) { acc[i][0] = 0ull; acc[i][1] = 0ull; }

    const int NT = K / 16;
    for (int kt = 0; kt < NT; kt++) {
        __syncthreads();

        float4 av2, wv2;
        if (kt + 1 < NT) {
            av2 = *(const float4*)Aptr;  Aptr += 16;
            wv2 = *(const float4*)Wptr;  Wptr += (size_t)16 * N;
        }

        const int cb = kt & 1;
        #pragma unroll
        for (int kk = 0; kk < 16; kk++) {
            float4 a4 = *(const float4*)&As[cb][kk][ty * 4];
            ulonglong2 w2 = *(const ulonglong2*)&Ws[cb][kk][tx * 4];
            const float a[4] = {a4.x, a4.y, a4.z, a4.w};
            #pragma unroll
            for (int i = 0; i < 4; i++) {
                u64 ad = pack2(a[i]);
                ffma2(acc[i][0], ad, w2.x);
                ffma2(acc[i][1], ad, w2.y);
            }
        }

        if (kt + 1 < NT) {
            const int nb = (kt + 1) & 1;
            As[nb][aq * 4 + 0][arow] = av2.x;
            As[nb][aq * 4 + 1][arow] = av2.y;
            As[nb][aq * 4 + 2][arow] = av2.z;
            As[nb][aq * 4 + 3][arow] = av2.w;
            *(float4*)&Ws[nb][wk][wq * 4] = wv2;
        }
    }

    const int row = by * 64 + ty * 4;
    const int col = bx * 64 + tx * 4;
    float bl[4];
    #pragma unroll
    for (int jj = 0; jj < 4; jj++) bl[jj] = bias[col + jj];

    #pragma unroll
    for (int i = 0; i < 4; i++) {
        float2 p0 = unpk(acc[i][0]);
        float2 p1 = unpk(acc[i][1]);
        float v[4] = {p0.x, p0.y, p1.x, p1.y};
        float4 o;
        float* op = &o.x;
        #pragma unroll
        for (int jj = 0; jj < 4; jj++) {
            float s = v[jj] + bl[jj];
            if (act) { float r = fmaxf(s, 0.0f); s = r * r; }
            op[jj] = s;
        }
        *(float4*)&C[(size_t)(row + i) * N + col] = o;
    }
}

// ---------------------------------------------------------------------------
// Flag-pipelined sequential scan, f32x2-packed batch pairs.
// h[:,j] += relu^2(h[:,i]*Whh[i,j] + Bhh[i,j]) for j > i, strict order in i.
// 16 chunks of 32 columns, one warp per chunk; smem flags, no block barriers.
// ---------------------------------------------------------------------------
__global__ __launch_bounds__(512) void scan_kernel(
    const float* __restrict__ Whh, const float* __restrict__ Bhh)
{
    const int j    = threadIdx.x;
    const int w    = j >> 5;
    const int l    = j & 31;
    const int row0 = blockIdx.x * NB;

    __shared__ __align__(16) float bc[NCH][CH][NB];
    __shared__ int flag[NCH];

    if (j < NCH) flag[j] = 0;
    __syncthreads();
    volatile int* vflag = flag;

    // h as 4 packed pairs: {b0,b1},{b2,b3},{b4,b5},{b6,b7}
    u64 h2[4];
    #pragma unroll
    for (int p = 0; p < 4; p++)
        h2[p] = packxy(g_h[(size_t)(row0 + 2 * p) * HID + j],
                       g_h[(size_t)(row0 + 2 * p + 1) * HID + j]);

    // ---- apply earlier chunks as they are published (16-deep halves) ----
    for (int c = 0; c < w; c++) {
        const int base = c << 5;
        float wv0[16], bv0[16];
        #pragma unroll
        for (int q = 0; q < 16; q++) {          // prefetch half 0 before spin
            wv0[q] = Whh[(size_t)(base + q) * HID + j];
            bv0[q] = Bhh[(size_t)(base + q) * HID + j];
        }
        while (vflag[c] == 0) { }
        __threadfence_block();

        float wv1[16], bv1[16];
        #pragma unroll
        for (int q = 0; q < 16; q++) {          // half 1 overlaps half-0 apply
            wv1[q] = Whh[(size_t)(base + 16 + q) * HID + j];
            bv1[q] = Bhh[(size_t)(base + 16 + q) * HID + j];
        }

        #pragma unroll
        for (int q = 0; q < 16; q++) {
            ulonglong2 s01 = *(const ulonglong2*)&bc[c][q][0];
            ulonglong2 s23 = *(const ulonglong2*)&bc[c][q][4];
            u64 s2[4] = {s01.x, s01.y, s23.x, s23.y};
            u64 wd = pack2(wv0[q]), bd = pack2(bv0[q]);
            #pragma unroll
            for (int p = 0; p < 4; p++) {
                u64 m = max2z(fma2v(s2[p], wd, bd));
                h2[p] = fma2v(m, m, h2[p]);
            }
        }
        #pragma unroll
        for (int q = 0; q < 16; q++) {
            ulonglong2 s01 = *(const ulonglong2*)&bc[c][16 + q][0];
            ulonglong2 s23 = *(const ulonglong2*)&bc[c][16 + q][4];
            u64 s2[4] = {s01.x, s01.y, s23.x, s23.y};
            u64 wd = pack2(wv1[q]), bd = pack2(bv1[q]);
            #pragma unroll
            for (int p = 0; p < 4; p++) {
                u64 m = max2z(fma2v(s2[p], wd, bd));
                h2[p] = fma2v(m, m, h2[p]);
            }
        }
    }

    // ---- intra-warp sequential scan of own chunk ----
    const int cbase = w << 5;
    #pragma unroll
    for (int half = 0; half < 2; half++) {
        float wr[16], br[16];
        #pragma unroll
        for (int q = 0; q < 16; q++) {
            int i = cbase + half * 16 + q;
            bool valid = (i < HID - 1);
            wr[q] = valid ? Whh[(size_t)i * HID + j] : 0.0f;
            br[q] = valid ? Bhh[(size_t)i * HID + j] : 0.0f;
        }
        #pragma unroll
        for (int q = 0; q < 16; q++) {
            const int il = half * 16 + q;
            u64 s2[4];
            #pragma unroll
            for (int p = 0; p < 4; p++)
                s2[p] = __shfl_sync(0xffffffffu, h2[p], il);
            if (l > il) {
                u64 wd = pack2(wr[q]), bd = pack2(br[q]);
                #pragma unroll
                for (int p = 0; p < 4; p++) {
                    u64 m = max2z(fma2v(s2[p], wd, bd));
                    h2[p] = fma2v(m, m, h2[p]);
                }
            }
        }
    }

    // ---- publish + final store ----
    if (w < NCH - 1) {
        *(ulonglong2*)&bc[w][l][0] = make_ulonglong2(h2[0], h2[1]);
        *(ulonglong2*)&bc[w][l][4] = make_ulonglong2(h2[2], h2[3]);
        __threadfence_block();
        if (l == 0) vflag[w] = 1;
    }
    #pragma unroll
    for (int p = 0; p < 4; p++) {
        float2 f = unpk(h2[p]);
        g_h[(size_t)(row0 + 2 * p) * HID + j]     = f.x;
        g_h[(size_t)(row0 + 2 * p + 1) * HID + j] = f.y;
    }
}

// ---------------------------------------------------------------------------
extern "C" void kernel_launch(void* const* d_in, const int* in_sizes, int n_in,
                              void* d_out, int out_size)
{
    const float* x     = (const float*)d_in[0];
    const float* W_in  = (const float*)d_in[1];
    const float* b_in  = (const float*)d_in[2];
    const float* W_hh  = (const float*)d_in[3];
    const float* b_hh  = (const float*)d_in[4];
    const float* W_out = (const float*)d_in[5];
    const float* b_out = (const float*)d_in[6];
    float* out = (float*)d_out;

    float* hptr = nullptr;
    cudaGetSymbolAddress((void**)&hptr, g_h);

    dim3 gblk(256);
    dim3 ggrid(HID / 64, BATCH / 64);
    gemm_kernel<<<ggrid, gblk>>>(x, W_in, b_in, hptr, BATCH, HID, DIN, 1);

    scan_kernel<<<BATCH / NB, 512>>>(W_hh, b_hh);

    dim3 ogrid(DOUT / 64, BATCH / 64);
    gemm_kernel<<<ogrid, gblk>>>(hptr, W_out, b_out, out, BATCH, DOUT, HID, 0);
}

// round 6
// speedup vs baseline: 1.6855x; 1.0165x over previous
#include <cuda_runtime.h>
#include <cuda_bf16.h>
#include <cstdint>

#define BATCH 1024
#define HIDN  512
#define KP    1536          // packed K: [hi | lo | hi]
#define NB    8             // batch rows per scan CTA
#define CH    32            // scan chunk width
#define NCHW  (HIDN / CH)   // 16 scan chunks
#define NCHUNK 24           // KP / 64

typedef unsigned long long u64;
typedef unsigned int u32;

__device__ float g_h[BATCH * HIDN];
__device__ __align__(16) __nv_bfloat16 g_A3[BATCH * KP];
__device__ __align__(16) __nv_bfloat16 g_B3in[HIDN * KP];
__device__ __align__(16) __nv_bfloat16 g_B3out[HIDN * KP];
__device__ __align__(16) __nv_bfloat16 g_H3[BATCH * KP];

// ---- f32x2 helpers (scan) ---------------------------------------------------
__device__ __forceinline__ u64 pack2(float v) {
    u64 r; asm("mov.b64 %0, {%1, %1};" : "=l"(r) : "f"(v)); return r;
}
__device__ __forceinline__ u64 packxy(float x, float y) {
    u64 r; asm("mov.b64 %0, {%1, %2};" : "=l"(r) : "f"(x), "f"(y)); return r;
}
__device__ __forceinline__ float2 unpk(u64 v) {
    float2 f; asm("mov.b64 {%0, %1}, %2;" : "=f"(f.x), "=f"(f.y) : "l"(v)); return f;
}
__device__ __forceinline__ u64 fma2v(u64 a, u64 b, u64 c) {
    u64 d; asm("fma.rn.f32x2 %0, %1, %2, %3;" : "=l"(d) : "l"(a), "l"(b), "l"(c)); return d;
}
__device__ __forceinline__ u64 max2z(u64 v) {
    u64 m;
    asm("{\n\t.reg .f32 a, b;\n\t"
        "mov.b64 {a, b}, %1;\n\t"
        "max.f32 a, a, 0f00000000;\n\t"
        "max.f32 b, b, 0f00000000;\n\t"
        "mov.b64 %0, {a, b};\n\t}"
        : "=l"(m) : "l"(v));
    return m;
}

// ---- misc helpers -----------------------------------------------------------
__device__ __forceinline__ u32 s2u(const void* p) {
    u32 a;
    asm("{ .reg .u64 t; cvta.to.shared.u64 t, %1; cvt.u32.u64 %0, t; }" : "=r"(a) : "l"(p));
    return a;
}
#define SWZ(x) ((x) ^ (((x) >> 3) & 0x70))

__device__ __forceinline__ void bsplit(float a, unsigned short& h, unsigned short& l) {
    __nv_bfloat16 hb = __float2bfloat16(a);
    __nv_bfloat16 lb = __float2bfloat16(a - __bfloat162float(hb));
    h = *(unsigned short*)&hb;
    l = *(unsigned short*)&lb;
}
__device__ __forceinline__ uint4 pack8(const unsigned short* s) {
    uint4 u;
    u.x = (u32)s[0] | ((u32)s[1] << 16);
    u.y = (u32)s[2] | ((u32)s[3] << 16);
    u.z = (u32)s[4] | ((u32)s[5] << 16);
    u.w = (u32)s[6] | ((u32)s[7] << 16);
    return u;
}

__device__ __forceinline__ void ldm4(u32 addr, u32& r0, u32& r1, u32& r2, u32& r3) {
    asm volatile("ldmatrix.sync.aligned.m8n8.x4.shared.b16 {%0,%1,%2,%3}, [%4];"
                 : "=r"(r0), "=r"(r1), "=r"(r2), "=r"(r3) : "r"(addr));
}
__device__ __forceinline__ void mma16816(float* c, const u32* a, const u32* b) {
    asm volatile("mma.sync.aligned.m16n8k16.row.col.f32.bf16.bf16.f32 "
                 "{%0,%1,%2,%3}, {%4,%5,%6,%7}, {%8,%9}, {%0,%1,%2,%3};"
                 : "+f"(c[0]), "+f"(c[1]), "+f"(c[2]), "+f"(c[3])
                 : "r"(a[0]), "r"(a[1]), "r"(a[2]), "r"(a[3]), "r"(b[0]), "r"(b[1]));
}

// ---------------------------------------------------------------------------
// convA: X [M,512] fp32 -> A3 [M,1536] bf16 = [hi | lo | hi]
// ---------------------------------------------------------------------------
__global__ __launch_bounds__(256) void convA(
    const float* __restrict__ X, __nv_bfloat16* __restrict__ A3)
{
    int t = blockIdx.x * 256 + threadIdx.x;   // one thread per 8 elems
    int m = t >> 6, k8 = (t & 63) << 3;
    float4 v0 = *(const float4*)(X + (size_t)m * 512 + k8);
    float4 v1 = *(const float4*)(X + (size_t)m * 512 + k8 + 4);
    float a[8] = {v0.x, v0.y, v0.z, v0.w, v1.x, v1.y, v1.z, v1.w};
    unsigned short hs[8], ls[8];
    #pragma unroll
    for (int e = 0; e < 8; e++) bsplit(a[e], hs[e], ls[e]);
    uint4 hp = pack8(hs), lp = pack8(ls);
    __nv_bfloat16* base = A3 + (size_t)m * KP + k8;
    *(uint4*)(base)        = hp;
    *(uint4*)(base + 512)  = lp;
    *(uint4*)(base + 1024) = hp;
}

// ---------------------------------------------------------------------------
// convW: W [512(k),512(n)] fp32 -> B3 [n][1536] bf16 = [Wh | Wh | Wl] (K-major)
// ---------------------------------------------------------------------------
__global__ __launch_bounds__(256) void convW(
    const float* __restrict__ W, __nv_bfloat16* __restrict__ B3)
{
    __shared__ float tile[64][65];
    const int kb = blockIdx.y * 64, nb = blockIdx.x * 64, tid = threadIdx.x;
    #pragma unroll
    for (int it = 0; it < 16; it++) {
        int idx = tid + it * 256, r = idx >> 6, cn = idx & 63;
        tile[r][cn] = W[(size_t)(kb + r) * 512 + nb + cn];
    }
    __syncthreads();
    const int nl = tid >> 2, kq = (tid & 3) << 4;
    const int row = nb + nl;
    #pragma unroll
    for (int g = 0; g < 2; g++) {
        unsigned short hs[8], ls[8];
        #pragma unroll
        for (int e = 0; e < 8; e++)
            bsplit(tile[kq + g * 8 + e][nl], hs[e], ls[e]);
        uint4 hp = pack8(hs), lp = pack8(ls);
        __nv_bfloat16* base = B3 + (size_t)row * KP + kb + kq + g * 8;
        *(uint4*)(base)        = hp;
        *(uint4*)(base + 512)  = hp;
        *(uint4*)(base + 1024) = lp;
    }
}

// ---------------------------------------------------------------------------
// Warp-MMA bf16 GEMM: C[1024,512] = act?(A3[1024,KP] . B3[512,KP]^T + bias)
// CTA 64x64 tile, 128 threads = 2x2 warps of 32x32 warp tiles.
// K staged in 64-elem chunks (128B rows, swizzled), double buffered,
// one barrier per chunk, LDG prefetch overlapped with HMMA compute.
// ---------------------------------------------------------------------------
__global__ __launch_bounds__(128) void mma_gemm(
    const __nv_bfloat16* __restrict__ A3, const __nv_bfloat16* __restrict__ B3,
    const float* __restrict__ bias, float* __restrict__ C, int act)
{
    __shared__ __align__(128) char As[2][8192];
    __shared__ __align__(128) char Bs[2][8192];

    const int tid = threadIdx.x, wid = tid >> 5, lane = tid & 31;
    const int wm = wid >> 1, wn = wid & 1;
    const int mbase = blockIdx.y * 64, nbase = blockIdx.x * 64;
    const u32 sA = s2u(&As[0][0]), sB = s2u(&Bs[0][0]);

    // per-lane ldmatrix offsets (relative to chunk buffer base)
    const int idx  = lane >> 3, lrow = lane & 7;
    u32 off_a[2][4], off_b[2][4];
    #pragma unroll
    for (int mt = 0; mt < 2; mt++)
        #pragma unroll
        for (int ks = 0; ks < 4; ks++) {
            int m_off = wm * 32 + mt * 16 + (idx & 1) * 8 + lrow;
            int kb    = ks * 32 + (idx >> 1) * 16;
            off_a[mt][ks] = SWZ(m_off * 128 + kb);
        }
    #pragma unroll
    for (int ng = 0; ng < 2; ng++)
        #pragma unroll
        for (int ks = 0; ks < 4; ks++) {
            int n_off = wn * 32 + ng * 16 + (idx >> 1) * 8 + lrow;
            int kb    = ks * 32 + (idx & 1) * 16;
            off_b[ng][ks] = SWZ(n_off * 128 + kb);
        }

    float acc[2][4][4];
    #pragma unroll
    for (int mt = 0; mt < 2; mt++)
        #pragma unroll
        for (int nt = 0; nt < 4; nt++)
            #pragma unroll
            for (int e = 0; e < 4; e++) acc[mt][nt][e] = 0.0f;

    // staging indices: per thread 4 uint4 for A, 4 for B per chunk
    const int sr = tid >> 3, sq = tid & 7;   // base row/quad; rows advance by 16/iter

    // prologue: chunk 0
    {
        #pragma unroll
        for (int i = 0; i < 4; i++) {
            int r = sr + i * 16;
            uint4 v = *(const uint4*)(A3 + (size_t)(mbase + r) * KP + sq * 8);
            *(uint4*)(As[0] + SWZ(r * 128 + sq * 16)) = v;
        }
        #pragma unroll
        for (int i = 0; i < 4; i++) {
            int r = sr + i * 16;
            uint4 v = *(const uint4*)(B3 + (size_t)(nbase + r) * KP + sq * 8);
            *(uint4*)(Bs[0] + SWZ(r * 128 + sq * 16)) = v;
        }
    }

    for (int c = 0; c < NCHUNK; c++) {
        __syncthreads();

        uint4 pa[4], pb[4];
        if (c + 1 < NCHUNK) {
            #pragma unroll
            for (int i = 0; i < 4; i++) {
                int r = sr + i * 16;
                pa[i] = *(const uint4*)(A3 + (size_t)(mbase + r) * KP + (c + 1) * 64 + sq * 8);
                pb[i] = *(const uint4*)(B3 + (size_t)(nbase + r) * KP + (c + 1) * 64 + sq * 8);
            }
        }

        const int cb = c & 1;
        const u32 ab = sA + cb * 8192, bb = sB + cb * 8192;
        #pragma unroll
        for (int ks = 0; ks < 4; ks++) {
            u32 af[2][4], bf[2][4];
            #pragma unroll
            for (int mt = 0; mt < 2; mt++)
                ldm4(ab + off_a[mt][ks], af[mt][0], af[mt][1], af[mt][2], af[mt][3]);
            #pragma unroll
            for (int ng = 0; ng < 2; ng++)
                ldm4(bb + off_b[ng][ks], bf[ng][0], bf[ng][1], bf[ng][2], bf[ng][3]);
            #pragma unroll
            for (int mt = 0; mt < 2; mt++)
                #pragma unroll
                for (int nt = 0; nt < 4; nt++)
                    mma16816(acc[mt][nt], af[mt], &bf[nt >> 1][(nt & 1) * 2]);
        }

        if (c + 1 < NCHUNK) {
            const int nb2 = (c + 1) & 1;
            #pragma unroll
            for (int i = 0; i < 4; i++) {
                int r = sr + i * 16;
                *(uint4*)(As[nb2] + SWZ(r * 128 + sq * 16)) = pa[i];
                *(uint4*)(Bs[nb2] + SWZ(r * 128 + sq * 16)) = pb[i];
            }
        }
    }

    // epilogue
    #pragma unroll
    for (int mt = 0; mt < 2; mt++) {
        const int row = mbase + wm * 32 + mt * 16 + (lane >> 2);
        #pragma unroll
        for (int nt = 0; nt < 4; nt++) {
            const int col = nbase + wn * 32 + nt * 8 + (lane & 3) * 2;
            float2 bv = *(const float2*)&bias[col];
            float2 o1 = make_float2(acc[mt][nt][0] + bv.x, acc[mt][nt][1] + bv.y);
            float2 o2 = make_float2(acc[mt][nt][2] + bv.x, acc[mt][nt][3] + bv.y);
            if (act) {
                float r;
                r = fmaxf(o1.x, 0.0f); o1.x = r * r;
                r = fmaxf(o1.y, 0.0f); o1.y = r * r;
                r = fmaxf(o2.x, 0.0f); o2.x = r * r;
                r = fmaxf(o2.y, 0.0f); o2.y = r * r;
            }
            *(float2*)&C[(size_t)row * HIDN + col]       = o1;
            *(float2*)&C[(size_t)(row + 8) * HIDN + col] = o2;
        }
    }
}

// ---------------------------------------------------------------------------
// Flag-pipelined sequential scan; tail writes bf16-split g_H3 directly.
// ---------------------------------------------------------------------------
__global__ __launch_bounds__(512) void scan_kernel(
    const float* __restrict__ Whh, const float* __restrict__ Bhh)
{
    const int j    = threadIdx.x;
    const int w    = j >> 5;
    const int l    = j & 31;
    const int row0 = blockIdx.x * NB;

    __shared__ __align__(16) float bc[NCHW][CH][NB];
    __shared__ int flag[NCHW];

    if (j < NCHW) flag[j] = 0;
    __syncthreads();
    volatile int* vflag = flag;

    u64 h2[4];
    #pragma unroll
    for (int p = 0; p < 4; p++)
        h2[p] = packxy(g_h[(size_t)(row0 + 2 * p) * HIDN + j],
                       g_h[(size_t)(row0 + 2 * p + 1) * HIDN + j]);

    for (int c = 0; c < w; c++) {
        const int base = c << 5;
        float wv0[16], bv0[16];
        #pragma unroll
        for (int q = 0; q < 16; q++) {
            wv0[q] = Whh[(size_t)(base + q) * HIDN + j];
            bv0[q] = Bhh[(size_t)(base + q) * HIDN + j];
        }
        while (vflag[c] == 0) { __nanosleep(64); }
        __threadfence_block();

        float wv1[16], bv1[16];
        #pragma unroll
        for (int q = 0; q < 16; q++) {
            wv1[q] = Whh[(size_t)(base + 16 + q) * HIDN + j];
            bv1[q] = Bhh[(size_t)(base + 16 + q) * HIDN + j];
        }

        #pragma unroll
        for (int q = 0; q < 16; q++) {
            ulonglong2 s01 = *(const ulonglong2*)&bc[c][q][0];
            ulonglong2 s23 = *(const ulonglong2*)&bc[c][q][4];
            u64 s2[4] = {s01.x, s01.y, s23.x, s23.y};
            u64 wd = pack2(wv0[q]), bd = pack2(bv0[q]);
            #pragma unroll
            for (int p = 0; p < 4; p++) {
                u64 m = max2z(fma2v(s2[p], wd, bd));
                h2[p] = fma2v(m, m, h2[p]);
            }
        }
        #pragma unroll
        for (int q = 0; q < 16; q++) {
            ulonglong2 s01 = *(const ulonglong2*)&bc[c][16 + q][0];
            ulonglong2 s23 = *(const ulonglong2*)&bc[c][16 + q][4];
            u64 s2[4] = {s01.x, s01.y, s23.x, s23.y};
            u64 wd = pack2(wv1[q]), bd = pack2(bv1[q]);
            #pragma unroll
            for (int p = 0; p < 4; p++) {
                u64 m = max2z(fma2v(s2[p], wd, bd));
                h2[p] = fma2v(m, m, h2[p]);
            }
        }
    }

    const int cbase = w << 5;
    #pragma unroll
    for (int half = 0; half < 2; half++) {
        float wr[16], br[16];
        #pragma unroll
        for (int q = 0; q < 16; q++) {
            int i = cbase + half * 16 + q;
            bool valid = (i < HIDN - 1);
            wr[q] = valid ? Whh[(size_t)i * HIDN + j] : 0.0f;
            br[q] = valid ? Bhh[(size_t)i * HIDN + j] : 0.0f;
        }
        #pragma unroll
        for (int q = 0; q < 16; q++) {
            const int il = half * 16 + q;
            u64 s2[4];
            #pragma unroll
            for (int p = 0; p < 4; p++)
                s2[p] = __shfl_sync(0xffffffffu, h2[p], il);
            if (l > il) {
                u64 wd = pack2(wr[q]), bd = pack2(br[q]);
                #pragma unroll
                for (int p = 0; p < 4; p++) {
                    u64 m = max2z(fma2v(s2[p], wd, bd));
                    h2[p] = fma2v(m, m, h2[p]);
                }
            }
        }
    }

    if (w < NCHW - 1) {
        *(ulonglong2*)&bc[w][l][0] = make_ulonglong2(h2[0], h2[1]);
        *(ulonglong2*)&bc[w][l][4] = make_ulonglong2(h2[2], h2[3]);
        __threadfence_block();
        if (l == 0) vflag[w] = 1;
    }

    // write bf16-split h directly for GEMM2
    #pragma unroll
    for (int p = 0; p < 4; p++) {
        float2 f = unpk(h2[p]);
        int r0 = row0 + 2 * p;
        unsigned short hh, ll;
        bsplit(f.x, hh, ll);
        *(unsigned short*)&g_H3[(size_t)r0 * KP + j]        = hh;
        *(unsigned short*)&g_H3[(size_t)r0 * KP + 512 + j]  = ll;
        *(unsigned short*)&g_H3[(size_t)r0 * KP + 1024 + j] = hh;
        bsplit(f.y, hh, ll);
        *(unsigned short*)&g_H3[(size_t)(r0 + 1) * KP + j]        = hh;
        *(unsigned short*)&g_H3[(size_t)(r0 + 1) * KP + 512 + j]  = ll;
        *(unsigned short*)&g_H3[(size_t)(r0 + 1) * KP + 1024 + j] = hh;
    }
}

// ---------------------------------------------------------------------------
extern "C" void kernel_launch(void* const* d_in, const int* in_sizes, int n_in,
                              void* d_out, int out_size)
{
    const float* x     = (const float*)d_in[0];
    const float* W_in  = (const float*)d_in[1];
    const float* b_in  = (const float*)d_in[2];
    const float* W_hh  = (const float*)d_in[3];
    const float* b_hh  = (const float*)d_in[4];
    const float* W_out = (const float*)d_in[5];
    const float* b_out = (const float*)d_in[6];
    float* out = (float*)d_out;

    float* hptr = nullptr;
    __nv_bfloat16 *a3 = nullptr, *b3i = nullptr, *b3o = nullptr, *h3 = nullptr;
    cudaGetSymbolAddress((void**)&hptr, g_h);
    cudaGetSymbolAddress((void**)&a3,  g_A3);
    cudaGetSymbolAddress((void**)&b3i, g_B3in);
    cudaGetSymbolAddress((void**)&b3o, g_B3out);
    cudaGetSymbolAddress((void**)&h3,  g_H3);

    convA<<<BATCH * 64 / 256, 256>>>(x, a3);
    convW<<<dim3(8, 8), 256>>>(W_in, b3i);
    convW<<<dim3(8, 8), 256>>>(W_out, b3o);

    mma_gemm<<<dim3(HIDN / 64, BATCH / 64), 128>>>(a3, b3i, b_in, hptr, 1);

    scan_kernel<<<BATCH / NB, 512>>>(W_hh, b_hh);

    mma_gemm<<<dim3(HIDN / 64, BATCH / 64), 128>>>(h3, b3o, b_out, out, 0);
}